// round 2
// baseline (speedup 1.0000x reference)
#include <cuda_runtime.h>
#include <math.h>

// ---------------- problem constants ----------------
#define BB 256      // batch
#define TT 128      // timesteps
#define FF 784      // input features
#define HH 1024     // hidden
#define CC 10       // classes
#define M1 (BB*TT)  // 32768 rows for the time-parallel GEMMs
#define BN_EPS 1e-3f

// ---------------- scratch (device globals; no runtime alloc allowed) -------
__device__ float g_feat[(size_t)M1 * HH];        // 128 MB  tanh(bn(tanh(x@W_fe+b)))
__device__ float g_zx  [(size_t)M1 * 4 * HH];    // 512 MB  feat@kernel + bias, all t
__device__ float g_hseq[(size_t)M1 * HH];        // 128 MB  (T,B,H) hidden states
__device__ float g_zh  [(size_t)BB * 4 * HH];    // 4 MB    h@rec_kernel, current step
__device__ float g_c   [(size_t)BB * HH];        // 1 MB    cell state

// ---------------- utility: zero a buffer -----------------------------------
__global__ void zero_kernel(float* __restrict__ p, int n) {
    int i = blockIdx.x * blockDim.x + threadIdx.x;
    if (i < n) p[i] = 0.0f;
}

// ---------------- tiled fp32 GEMM ------------------------------------------
// C[M,N] = epilogue(A[M,K] @ B[K,N])
// EPI 0: none   1: feat epilogue (tanh,BN,tanh)   2: +bias
template<int BM, int BN, int BK, int TM, int TN, int EPI>
__global__ void __launch_bounds__((BM/TM)*(BN/TN))
gemm_kernel(const float* __restrict__ A, const float* __restrict__ B,
            float* __restrict__ C, int M, int N, int K,
            const float* __restrict__ p0, const float* __restrict__ p1,
            const float* __restrict__ p2, const float* __restrict__ p3,
            const float* __restrict__ p4)
{
    constexpr int THREADS = (BM/TM) * (BN/TN);
    __shared__ float As[BK][BM];
    __shared__ float Bs[BK][BN];

    const int tid = threadIdx.x;
    const int tx  = tid % (BN/TN);
    const int ty  = tid / (BN/TN);
    const int row0 = blockIdx.y * BM;
    const int col0 = blockIdx.x * BN;

    float acc[TM][TN];
#pragma unroll
    for (int i = 0; i < TM; i++)
#pragma unroll
        for (int j = 0; j < TN; j++) acc[i][j] = 0.0f;

    for (int k0 = 0; k0 < K; k0 += BK) {
        // load A tile (transposed into smem), vectorized float4
#pragma unroll
        for (int i = tid * 4; i < BM * BK; i += THREADS * 4) {
            int m = i / BK, k = i % BK;
            float4 v = *(const float4*)&A[(size_t)(row0 + m) * K + k0 + k];
            As[k + 0][m] = v.x; As[k + 1][m] = v.y;
            As[k + 2][m] = v.z; As[k + 3][m] = v.w;
        }
        // load B tile, vectorized float4
#pragma unroll
        for (int i = tid * 4; i < BK * BN; i += THREADS * 4) {
            int k = i / BN, n = i % BN;
            float4 v = *(const float4*)&B[(size_t)(k0 + k) * N + col0 + n];
            *(float4*)&Bs[k][n] = v;
        }
        __syncthreads();

#pragma unroll
        for (int kk = 0; kk < BK; kk++) {
            float ra[TM], rb[TN];
#pragma unroll
            for (int i = 0; i < TM; i += 4) {
                float4 v = *(const float4*)&As[kk][ty * TM + i];
                ra[i] = v.x; ra[i+1] = v.y; ra[i+2] = v.z; ra[i+3] = v.w;
            }
#pragma unroll
            for (int j = 0; j < TN; j += 4) {
                float4 v = *(const float4*)&Bs[kk][tx * TN + j];
                rb[j] = v.x; rb[j+1] = v.y; rb[j+2] = v.z; rb[j+3] = v.w;
            }
#pragma unroll
            for (int i = 0; i < TM; i++)
#pragma unroll
                for (int j = 0; j < TN; j++)
                    acc[i][j] = fmaf(ra[i], rb[j], acc[i][j]);
        }
        __syncthreads();
    }

    // epilogue + store
#pragma unroll
    for (int i = 0; i < TM; i++) {
        int m = row0 + ty * TM + i;
#pragma unroll
        for (int j = 0; j < TN; j++) {
            int n = col0 + tx * TN + j;
            float v = acc[i][j];
            if (EPI == 1) {
                v = tanhf(v + p0[n]);                                   // dense tanh + bias
                v = (v - p3[n]) * rsqrtf(p4[n] + BN_EPS) * p1[n] + p2[n]; // BN
                v = tanhf(v);                                            // act
            } else if (EPI == 2) {
                v += p0[n];                                              // lstm bias
            }
            C[(size_t)m * N + n] = v;
        }
    }
}

// ---------------- LSTM pointwise gates --------------------------------------
__global__ void gates_kernel(const float* __restrict__ Zx, const float* __restrict__ Zh,
                             float* __restrict__ c, float* __restrict__ hout,
                             const float* __restrict__ pi, const float* __restrict__ pf,
                             const float* __restrict__ po, int t)
{
    int j = blockIdx.x * blockDim.x + threadIdx.x;   // 0..H-1
    int b = blockIdx.y;                              // 0..B-1
    size_t zr = ((size_t)b * TT + t) * (4 * HH);
    size_t hr = (size_t)b * (4 * HH);

    float cc = c[(size_t)b * HH + j];
    float zi = Zx[zr + 0*HH + j] + Zh[hr + 0*HH + j];
    float zf = Zx[zr + 1*HH + j] + Zh[hr + 1*HH + j];
    float zc = Zx[zr + 2*HH + j] + Zh[hr + 2*HH + j];
    float zo = Zx[zr + 3*HH + j] + Zh[hr + 3*HH + j];

    float ig = 1.0f / (1.0f + expf(-(zi + cc * pi[j])));
    float fg = 1.0f / (1.0f + expf(-(zf + cc * pf[j])));
    float cn = fg * cc + ig * tanhf(zc);
    float og = 1.0f / (1.0f + expf(-(zo + cn * po[j])));

    c[(size_t)b * HH + j]    = cn;
    hout[(size_t)b * HH + j] = og * tanhf(cn);
}

// ---------------- final BN -> tanh -> Dense(H,10) ----------------------------
__global__ void logits_kernel(const float* __restrict__ hseq,
                              const float* __restrict__ g2, const float* __restrict__ b2,
                              const float* __restrict__ m2, const float* __restrict__ v2,
                              const float* __restrict__ Wout, float* __restrict__ out)
{
    int row = blockIdx.x;            // = t*BB + b (hseq is (T,B,H))
    int t = row / BB, b = row % BB;
    int tid = threadIdx.x;           // 256 threads, each handles 4 consecutive k

    float a[CC];
#pragma unroll
    for (int c2 = 0; c2 < CC; c2++) a[c2] = 0.0f;

    float4 hv = *(const float4*)(hseq + (size_t)row * HH + tid * 4);
    float4 gv = *(const float4*)(g2 + tid * 4);
    float4 bv = *(const float4*)(b2 + tid * 4);
    float4 mv = *(const float4*)(m2 + tid * 4);
    float4 vv = *(const float4*)(v2 + tid * 4);

    float h4[4] = {hv.x, hv.y, hv.z, hv.w};
    float G4[4] = {gv.x, gv.y, gv.z, gv.w};
    float B4[4] = {bv.x, bv.y, bv.z, bv.w};
    float M4[4] = {mv.x, mv.y, mv.z, mv.w};
    float V4[4] = {vv.x, vv.y, vv.z, vv.w};

#pragma unroll
    for (int s = 0; s < 4; s++) {
        int k = tid * 4 + s;
        float y = tanhf((h4[s] - M4[s]) * rsqrtf(V4[s] + BN_EPS) * G4[s] + B4[s]);
        const float* wr = Wout + (size_t)k * CC;
#pragma unroll
        for (int c2 = 0; c2 < CC; c2++)
            a[c2] = fmaf(y, wr[c2], a[c2]);
    }

    // warp reduce then block combine
#pragma unroll
    for (int off = 16; off > 0; off >>= 1)
#pragma unroll
        for (int c2 = 0; c2 < CC; c2++)
            a[c2] += __shfl_down_sync(0xffffffffu, a[c2], off);

    __shared__ float sacc[CC];
    if (tid < CC) sacc[tid] = 0.0f;
    __syncthreads();
    if ((tid & 31) == 0)
#pragma unroll
        for (int c2 = 0; c2 < CC; c2++) atomicAdd(&sacc[c2], a[c2]);
    __syncthreads();
    if (tid < CC)
        out[((size_t)b * TT + t) * CC + tid] = sacc[tid];
}

// ---------------- launcher ----------------------------------------------------
extern "C" void kernel_launch(void* const* d_in, const int* in_sizes, int n_in,
                              void* d_out, int out_size)
{
    const float* x      = (const float*)d_in[0];
    const float* W_fe   = (const float*)d_in[1];
    const float* b_fe   = (const float*)d_in[2];
    const float* gamma1 = (const float*)d_in[3];
    const float* beta1  = (const float*)d_in[4];
    const float* mean1  = (const float*)d_in[5];
    const float* var1   = (const float*)d_in[6];
    const float* Wg     = (const float*)d_in[7];   // kernel (H, 4H)
    const float* Wr     = (const float*)d_in[8];   // rec_kernel (H, 4H)
    const float* bias   = (const float*)d_in[9];
    const float* pi     = (const float*)d_in[10];
    const float* pf     = (const float*)d_in[11];
    const float* po     = (const float*)d_in[12];
    const float* gamma2 = (const float*)d_in[13];
    const float* beta2  = (const float*)d_in[14];
    const float* mean2  = (const float*)d_in[15];
    const float* var2   = (const float*)d_in[16];
    const float* W_out  = (const float*)d_in[17];
    float* out = (float*)d_out;

    float *feat, *zx, *hseq, *zh, *cbuf;
    cudaGetSymbolAddress((void**)&feat, g_feat);
    cudaGetSymbolAddress((void**)&zx,   g_zx);
    cudaGetSymbolAddress((void**)&hseq, g_hseq);
    cudaGetSymbolAddress((void**)&zh,   g_zh);
    cudaGetSymbolAddress((void**)&cbuf, g_c);

    // zero cell state and first-step Zh
    zero_kernel<<<(BB*HH + 255)/256, 256>>>(cbuf, BB*HH);
    zero_kernel<<<(BB*4*HH + 255)/256, 256>>>(zh, BB*4*HH);

    // 1) feat = tanh(BN(tanh(x @ W_fe + b_fe)))   [32768 x 1024, K=784]
    {
        dim3 grid(HH/128, M1/128);
        gemm_kernel<128,128,16,8,8,1><<<grid, 256>>>(
            x, W_fe, feat, M1, HH, FF, b_fe, gamma1, beta1, mean1, var1);
    }
    // 2) Zx = feat @ kernel + bias                [32768 x 4096, K=1024]
    {
        dim3 grid(4*HH/128, M1/128);
        gemm_kernel<128,128,16,8,8,2><<<grid, 256>>>(
            feat, Wg, zx, M1, 4*HH, HH, bias, nullptr, nullptr, nullptr, nullptr);
    }
    // 3) recurrence
    {
        dim3 ggate(HH/256, BB);
        gates_kernel<<<ggate, 256>>>(zx, zh, cbuf, hseq, pi, pf, po, 0);
        dim3 gzh(4*HH/64, BB/64);
        for (int t = 1; t < TT; t++) {
            gemm_kernel<64,64,16,4,4,0><<<gzh, 256>>>(
                hseq + (size_t)(t-1)*BB*HH, Wr, zh, BB, 4*HH, HH,
                nullptr, nullptr, nullptr, nullptr, nullptr);
            gates_kernel<<<ggate, 256>>>(zx, zh, cbuf,
                                         hseq + (size_t)t*BB*HH, pi, pf, po, t);
        }
    }
    // 4) out = tanh(BN(hseq)) @ W_out             [32768 x 10]
    logits_kernel<<<M1, 256>>>(hseq, gamma2, beta2, mean2, var2, W_out, out);
}

// round 3
// speedup vs baseline: 2.5112x; 2.5112x over previous
#include <cuda_runtime.h>
#include <math.h>
#include <stdint.h>

// ---------------- problem constants ----------------
#define BB 256      // batch
#define TT 128      // timesteps
#define FF 784      // input features
#define HH 1024     // hidden
#define CC 10       // classes
#define M1 (BB*TT)  // 32768 rows for the time-parallel GEMMs
#define BN_EPS 1e-3f

// ---------------- scratch (device globals) ----------------
__device__ float g_feat[(size_t)M1 * HH];
__device__ float g_zx  [(size_t)M1 * 4 * HH];
__device__ float g_hseq[(size_t)M1 * HH];
__device__ float g_zh  [(size_t)BB * 4 * HH];
__device__ float g_c   [(size_t)BB * HH];

// ---------------- helpers ----------------
__device__ __forceinline__ uint32_t f2tf(float f) {
    uint32_t u;
    asm("cvt.rna.tf32.f32 %0, %1;" : "=r"(u) : "f"(f));
    return u;
}

__device__ __forceinline__ void cp16(void* dst, const void* src) {
    uint32_t d = (uint32_t)__cvta_generic_to_shared(dst);
    asm volatile("cp.async.cg.shared.global [%0], [%1], 16;" :: "r"(d), "l"(src));
}
#define CP_COMMIT asm volatile("cp.async.commit_group;")
#define CP_WAIT1  asm volatile("cp.async.wait_group 1;")
#define CP_WAIT0  asm volatile("cp.async.wait_group 0;")

__device__ __forceinline__ void mma_tf32(float* d, const uint32_t* a, const uint32_t* b) {
    asm volatile(
        "mma.sync.aligned.m16n8k8.row.col.f32.tf32.tf32.f32 "
        "{%0,%1,%2,%3}, {%4,%5,%6,%7}, {%8,%9}, {%0,%1,%2,%3};"
        : "+f"(d[0]), "+f"(d[1]), "+f"(d[2]), "+f"(d[3])
        : "r"(a[0]), "r"(a[1]), "r"(a[2]), "r"(a[3]),
          "r"(b[0]), "r"(b[1]));
}

__global__ void zero_kernel(float* __restrict__ p, int n) {
    int i = blockIdx.x * blockDim.x + threadIdx.x;
    if (i < n) p[i] = 0.0f;
}

// ---------------- tf32 tensor-core GEMM -------------------------------------
// C[M,N] = epilogue(A[M,K] @ B[K,N])
// EPI 0: none   1: feat epilogue (tanh,BN,tanh)   2: +bias
// Requirements: M%BM==0, N%BN==0, K%BK==0, all row-major fp32.
template<int BM, int BN, int BK, int WM, int WN, int EPI>
__global__ void __launch_bounds__((BM/WM)*(BN/WN)*32)
gemm_tf32(const float* __restrict__ A, const float* __restrict__ B,
          float* __restrict__ C, int M, int N, int K,
          const float* __restrict__ p0, const float* __restrict__ p1,
          const float* __restrict__ p2, const float* __restrict__ p3,
          const float* __restrict__ p4)
{
    constexpr int WARPS_N = BN / WN;
    constexpr int THREADS = (BM/WM) * (BN/WN) * 32;
    constexpr int MI = WM / 16;      // m16 atoms per warp
    constexpr int NI = WN / 8;       // n8 atoms per warp
    constexpr int KS = BK / 8;       // k8 steps per smem tile
    constexpr int AST = BK + 4;      // A smem row stride (words) -> conflict free
    constexpr int BST = BN + 8;      // B smem row stride; (BN+8)%32==8 -> conflict free
    constexpr int AQ = BM * BK / 4;  // float4 chunks in A tile
    constexpr int BQ = BK * BN / 4;

    __shared__ float As[2][BM * AST];
    __shared__ float Bs[2][BK * BST];

    const int tid  = threadIdx.x;
    const int lane = tid & 31;
    const int warp = tid >> 5;
    const int wm   = (warp / WARPS_N) * WM;
    const int wn   = (warp % WARPS_N) * WN;
    const int row0 = blockIdx.y * BM;
    const int col0 = blockIdx.x * BN;

    float acc[MI][NI][4];
#pragma unroll
    for (int mi = 0; mi < MI; mi++)
#pragma unroll
        for (int ni = 0; ni < NI; ni++)
#pragma unroll
            for (int r = 0; r < 4; r++) acc[mi][ni][r] = 0.0f;

    const int KT = K / BK;

    // ---- prologue: stage tile 0 ----
    {
#pragma unroll
        for (int q = tid; q < AQ; q += THREADS) {
            int r = q / (BK/4), c = (q % (BK/4)) * 4;
            cp16(&As[0][r * AST + c], A + (size_t)(row0 + r) * K + c);
        }
#pragma unroll
        for (int q = tid; q < BQ; q += THREADS) {
            int r = q / (BN/4), c = (q % (BN/4)) * 4;
            cp16(&Bs[0][r * BST + c], B + (size_t)r * N + col0 + c);
        }
        CP_COMMIT;
    }

#pragma unroll 1
    for (int kt = 0; kt < KT; kt++) {
        const int cur = kt & 1;
        if (kt + 1 < KT) {
            const int k0 = (kt + 1) * BK;
            const int nxt = cur ^ 1;
#pragma unroll
            for (int q = tid; q < AQ; q += THREADS) {
                int r = q / (BK/4), c = (q % (BK/4)) * 4;
                cp16(&As[nxt][r * AST + c], A + (size_t)(row0 + r) * K + k0 + c);
            }
#pragma unroll
            for (int q = tid; q < BQ; q += THREADS) {
                int r = q / (BN/4), c = (q % (BN/4)) * 4;
                cp16(&Bs[nxt][r * BST + c], B + (size_t)(k0 + r) * N + col0 + c);
            }
            CP_COMMIT;
            CP_WAIT1;
        } else {
            CP_WAIT0;
        }
        __syncthreads();

        // ---- compute on buffer `cur` ----
#pragma unroll
        for (int ks = 0; ks < KS; ks++) {
            uint32_t afr[MI][4];
            uint32_t bfr[NI][2];
            const int ar = lane >> 2;          // row-in-atom
            const int ac = ks * 8 + (lane & 3);
#pragma unroll
            for (int mi = 0; mi < MI; mi++) {
                const float* base = &As[cur][(wm + mi * 16 + ar) * AST + ac];
                afr[mi][0] = f2tf(base[0]);
                afr[mi][1] = f2tf(base[8 * AST]);
                afr[mi][2] = f2tf(base[4]);
                afr[mi][3] = f2tf(base[8 * AST + 4]);
            }
            const int bk = ks * 8 + (lane & 3);
            const int bn = lane >> 2;
#pragma unroll
            for (int ni = 0; ni < NI; ni++) {
                const float* base = &Bs[cur][bk * BST + wn + ni * 8 + bn];
                bfr[ni][0] = f2tf(base[0]);
                bfr[ni][1] = f2tf(base[4 * BST]);
            }
#pragma unroll
            for (int mi = 0; mi < MI; mi++)
#pragma unroll
                for (int ni = 0; ni < NI; ni++)
                    mma_tf32(acc[mi][ni], afr[mi], bfr[ni]);
        }
        __syncthreads();
    }

    // ---- epilogue + store ----
#pragma unroll
    for (int mi = 0; mi < MI; mi++) {
#pragma unroll
        for (int ni = 0; ni < NI; ni++) {
            const int r0 = row0 + wm + mi * 16 + (lane >> 2);
            const int c0 = col0 + wn + ni * 8 + 2 * (lane & 3);
#pragma unroll
            for (int half = 0; half < 2; half++) {
                const int rr = r0 + half * 8;
#pragma unroll
                for (int e = 0; e < 2; e++) {
                    const int nn = c0 + e;
                    float v = acc[mi][ni][half * 2 + e];
                    if (EPI == 1) {
                        v = tanhf(v + p0[nn]);
                        v = (v - p3[nn]) * rsqrtf(p4[nn] + BN_EPS) * p1[nn] + p2[nn];
                        v = tanhf(v);
                    } else if (EPI == 2) {
                        v += p0[nn];
                    }
                    C[(size_t)rr * N + nn] = v;
                }
            }
        }
    }
}

// ---------------- LSTM pointwise gates --------------------------------------
__global__ void gates_kernel(const float* __restrict__ Zx, const float* __restrict__ Zh,
                             float* __restrict__ c, float* __restrict__ hout,
                             const float* __restrict__ pi, const float* __restrict__ pf,
                             const float* __restrict__ po, int t)
{
    int j = blockIdx.x * blockDim.x + threadIdx.x;   // 0..H-1
    int b = blockIdx.y;                              // 0..B-1
    size_t zr = ((size_t)b * TT + t) * (4 * HH);
    size_t hr = (size_t)b * (4 * HH);

    float cc = c[(size_t)b * HH + j];
    float zi = Zx[zr + 0*HH + j] + Zh[hr + 0*HH + j];
    float zf = Zx[zr + 1*HH + j] + Zh[hr + 1*HH + j];
    float zc = Zx[zr + 2*HH + j] + Zh[hr + 2*HH + j];
    float zo = Zx[zr + 3*HH + j] + Zh[hr + 3*HH + j];

    float ig = 1.0f / (1.0f + expf(-(zi + cc * pi[j])));
    float fg = 1.0f / (1.0f + expf(-(zf + cc * pf[j])));
    float cn = fg * cc + ig * tanhf(zc);
    float og = 1.0f / (1.0f + expf(-(zo + cn * po[j])));

    c[(size_t)b * HH + j]    = cn;
    hout[(size_t)b * HH + j] = og * tanhf(cn);
}

// ---------------- final BN -> tanh -> Dense(H,10) ----------------------------
__global__ void logits_kernel(const float* __restrict__ hseq,
                              const float* __restrict__ g2, const float* __restrict__ b2,
                              const float* __restrict__ m2, const float* __restrict__ v2,
                              const float* __restrict__ Wout, float* __restrict__ out)
{
    int row = blockIdx.x;            // = t*BB + b (hseq is (T,B,H))
    int t = row / BB, b = row % BB;
    int tid = threadIdx.x;           // 256 threads, each handles 4 consecutive k

    float a[CC];
#pragma unroll
    for (int c2 = 0; c2 < CC; c2++) a[c2] = 0.0f;

    float4 hv = *(const float4*)(hseq + (size_t)row * HH + tid * 4);
    float4 gv = *(const float4*)(g2 + tid * 4);
    float4 bv = *(const float4*)(b2 + tid * 4);
    float4 mv = *(const float4*)(m2 + tid * 4);
    float4 vv = *(const float4*)(v2 + tid * 4);

    float h4[4] = {hv.x, hv.y, hv.z, hv.w};
    float G4[4] = {gv.x, gv.y, gv.z, gv.w};
    float B4[4] = {bv.x, bv.y, bv.z, bv.w};
    float M4[4] = {mv.x, mv.y, mv.z, mv.w};
    float V4[4] = {vv.x, vv.y, vv.z, vv.w};

#pragma unroll
    for (int s = 0; s < 4; s++) {
        int k = tid * 4 + s;
        float y = tanhf((h4[s] - M4[s]) * rsqrtf(V4[s] + BN_EPS) * G4[s] + B4[s]);
        const float* wr = Wout + (size_t)k * CC;
#pragma unroll
        for (int c2 = 0; c2 < CC; c2++)
            a[c2] = fmaf(y, wr[c2], a[c2]);
    }

#pragma unroll
    for (int off = 16; off > 0; off >>= 1)
#pragma unroll
        for (int c2 = 0; c2 < CC; c2++)
            a[c2] += __shfl_down_sync(0xffffffffu, a[c2], off);

    __shared__ float sacc[CC];
    if (tid < CC) sacc[tid] = 0.0f;
    __syncthreads();
    if ((tid & 31) == 0)
#pragma unroll
        for (int c2 = 0; c2 < CC; c2++) atomicAdd(&sacc[c2], a[c2]);
    __syncthreads();
    if (tid < CC)
        out[((size_t)b * TT + t) * CC + tid] = sacc[tid];
}

// ---------------- launcher ----------------------------------------------------
extern "C" void kernel_launch(void* const* d_in, const int* in_sizes, int n_in,
                              void* d_out, int out_size)
{
    const float* x      = (const float*)d_in[0];
    const float* W_fe   = (const float*)d_in[1];
    const float* b_fe   = (const float*)d_in[2];
    const float* gamma1 = (const float*)d_in[3];
    const float* beta1  = (const float*)d_in[4];
    const float* mean1  = (const float*)d_in[5];
    const float* var1   = (const float*)d_in[6];
    const float* Wg     = (const float*)d_in[7];   // kernel (H, 4H)
    const float* Wr     = (const float*)d_in[8];   // rec_kernel (H, 4H)
    const float* bias   = (const float*)d_in[9];
    const float* pi     = (const float*)d_in[10];
    const float* pf     = (const float*)d_in[11];
    const float* po     = (const float*)d_in[12];
    const float* gamma2 = (const float*)d_in[13];
    const float* beta2  = (const float*)d_in[14];
    const float* mean2  = (const float*)d_in[15];
    const float* var2   = (const float*)d_in[16];
    const float* W_out  = (const float*)d_in[17];
    float* out = (float*)d_out;

    float *feat, *zx, *hseq, *zh, *cbuf;
    cudaGetSymbolAddress((void**)&feat, g_feat);
    cudaGetSymbolAddress((void**)&zx,   g_zx);
    cudaGetSymbolAddress((void**)&hseq, g_hseq);
    cudaGetSymbolAddress((void**)&zh,   g_zh);
    cudaGetSymbolAddress((void**)&cbuf, g_c);

    // zero cell state and first-step Zh
    zero_kernel<<<(BB*HH + 255)/256, 256>>>(cbuf, BB*HH);
    zero_kernel<<<(BB*4*HH + 255)/256, 256>>>(zh, BB*4*HH);

    // 1) feat = tanh(BN(tanh(x @ W_fe + b_fe)))   [32768 x 1024, K=784]
    {
        dim3 grid(HH/128, M1/128);
        gemm_tf32<128,128,16,32,64,1><<<grid, 256>>>(
            x, W_fe, feat, M1, HH, FF, b_fe, gamma1, beta1, mean1, var1);
    }
    // 2) Zx = feat @ kernel + bias                [32768 x 4096, K=1024]
    {
        dim3 grid(4*HH/128, M1/128);
        gemm_tf32<128,128,16,32,64,2><<<grid, 256>>>(
            feat, Wg, zx, M1, 4*HH, HH, bias, nullptr, nullptr, nullptr, nullptr);
    }
    // 3) recurrence
    {
        dim3 ggate(HH/256, BB);
        gates_kernel<<<ggate, 256>>>(zx, zh, cbuf, hseq, pi, pf, po, 0);
        dim3 gzh(4*HH/64, BB/64);   // 64 x 4 = 256 CTAs
        for (int t = 1; t < TT; t++) {
            gemm_tf32<64,64,16,32,32,0><<<gzh, 128>>>(
                hseq + (size_t)(t-1)*BB*HH, Wr, zh, BB, 4*HH, HH,
                nullptr, nullptr, nullptr, nullptr, nullptr);
            gates_kernel<<<ggate, 256>>>(zx, zh, cbuf,
                                         hseq + (size_t)t*BB*HH, pi, pf, po, t);
        }
    }
    // 4) out = tanh(BN(hseq)) @ W_out             [32768 x 10]
    logits_kernel<<<M1, 256>>>(hseq, gamma2, beta2, mean2, var2, W_out, out);
}